// round 1
// baseline (speedup 1.0000x reference)
#include <cuda_runtime.h>
#include <math.h>

#define NB 16384
#define ND 256

static __device__ float g_qn[NB * ND];   // normalized Q, pre-scaled by log2(e)/T
static __device__ float g_dn[NB * ND];   // normalized D
static __device__ float g_rowsum[NB];
static __device__ float g_colsum[NB];

__global__ void zero_kernel(float* out) {
    int i = blockIdx.x * blockDim.x + threadIdx.x;
    if (i < NB) { g_rowsum[i] = 0.0f; g_colsum[i] = 0.0f; }
    if (i == 0) out[0] = 0.0f;
}

// One warp per row: L2-normalize 256 floats, multiply by `scale`.
__global__ void normalize_kernel(const float* __restrict__ in,
                                 float* __restrict__ out, float scale) {
    int row = blockIdx.x * 8 + threadIdx.y;
    int lane = threadIdx.x;
    const float4* src = reinterpret_cast<const float4*>(in + (size_t)row * ND);
    float4* dst = reinterpret_cast<float4*>(out + (size_t)row * ND);
    float4 v0 = src[lane];
    float4 v1 = src[lane + 32];
    float ss = v0.x * v0.x + v0.y * v0.y + v0.z * v0.z + v0.w * v0.w
             + v1.x * v1.x + v1.y * v1.y + v1.z * v1.z + v1.w * v1.w;
#pragma unroll
    for (int o = 16; o > 0; o >>= 1) ss += __shfl_xor_sync(0xFFFFFFFFu, ss, o);
    float inv = scale / fmaxf(sqrtf(ss), 1e-12f);
    v0.x *= inv; v0.y *= inv; v0.z *= inv; v0.w *= inv;
    v1.x *= inv; v1.y *= inv; v1.z *= inv; v1.w *= inv;
    dst[lane] = v0;
    dst[lane + 32] = v1;
}

__device__ __forceinline__ float ex2_approx(float x) {
    float r;
    asm("ex2.approx.f32 %0, %1;" : "=f"(r) : "f"(x));
    return r;
}

// Fused: C-tile = Qn * Dn^T (output is already the exp2 argument),
// epilogue: e = 2^t, accumulate row/col partial sums, atomicAdd to global.
#define BM 128
#define BN 128
#define BK 8
#define TM 8
#define TN 8

__global__ void __launch_bounds__(256, 2) gemm_lse_kernel() {
    __shared__ float As[BK][BM];
    __shared__ float Bs[BK][BN];
    __shared__ float red[128][17];  // padded reduction buffer

    int bi = blockIdx.y * BM;
    int bj = blockIdx.x * BN;
    int tid = threadIdx.x;
    int tx = tid & 15;       // 0..15 (col group)
    int ty = tid >> 4;       // 0..15 (row group)

    // global load mapping: 256 threads, 128 rows x 2 float4 along k
    int lrow = tid >> 1;
    int lk = (tid & 1) * 4;
    const float* Aptr = g_qn + (size_t)(bi + lrow) * ND + lk;
    const float* Bptr = g_dn + (size_t)(bj + lrow) * ND + lk;

    float acc[TM][TN];
#pragma unroll
    for (int i = 0; i < TM; i++)
#pragma unroll
        for (int j = 0; j < TN; j++) acc[i][j] = 0.0f;

    for (int k0 = 0; k0 < ND; k0 += BK) {
        float4 a = *reinterpret_cast<const float4*>(Aptr + k0);
        float4 b = *reinterpret_cast<const float4*>(Bptr + k0);
        __syncthreads();
        As[lk + 0][lrow] = a.x; As[lk + 1][lrow] = a.y;
        As[lk + 2][lrow] = a.z; As[lk + 3][lrow] = a.w;
        Bs[lk + 0][lrow] = b.x; Bs[lk + 1][lrow] = b.y;
        Bs[lk + 2][lrow] = b.z; Bs[lk + 3][lrow] = b.w;
        __syncthreads();
#pragma unroll
        for (int kk = 0; kk < BK; kk++) {
            float4 a0 = *reinterpret_cast<const float4*>(&As[kk][ty * TM]);
            float4 a1 = *reinterpret_cast<const float4*>(&As[kk][ty * TM + 4]);
            float4 b0 = *reinterpret_cast<const float4*>(&Bs[kk][tx * TN]);
            float4 b1 = *reinterpret_cast<const float4*>(&Bs[kk][tx * TN + 4]);
            float af[TM] = {a0.x, a0.y, a0.z, a0.w, a1.x, a1.y, a1.z, a1.w};
            float bf[TN] = {b0.x, b0.y, b0.z, b0.w, b1.x, b1.y, b1.z, b1.w};
#pragma unroll
            for (int i = 0; i < TM; i++)
#pragma unroll
                for (int j = 0; j < TN; j++)
                    acc[i][j] = fmaf(af[i], bf[j], acc[i][j]);
        }
    }

    // epilogue: exp2 and per-thread row/col partials
    float rsum[TM], csum[TN];
#pragma unroll
    for (int i = 0; i < TM; i++) rsum[i] = 0.0f;
#pragma unroll
    for (int j = 0; j < TN; j++) csum[j] = 0.0f;
#pragma unroll
    for (int i = 0; i < TM; i++) {
#pragma unroll
        for (int j = 0; j < TN; j++) {
            float e = ex2_approx(acc[i][j]);
            rsum[i] += e;
            csum[j] += e;
        }
    }

    // row reduction: row r's partials live in the 16 tx-threads
    __syncthreads();
#pragma unroll
    for (int i = 0; i < TM; i++) red[ty * TM + i][tx] = rsum[i];
    __syncthreads();
    if (tid < 128) {
        float s = 0.0f;
#pragma unroll
        for (int t = 0; t < 16; t++) s += red[tid][t];
        atomicAdd(&g_rowsum[bi + tid], s);
    }

    // col reduction: col c's partials live in the 16 ty-threads
    __syncthreads();
#pragma unroll
    for (int j = 0; j < TN; j++) red[tx * TN + j][ty] = csum[j];
    __syncthreads();
    if (tid < 128) {
        float s = 0.0f;
#pragma unroll
        for (int t = 0; t < 16; t++) s += red[tid][t];
        atomicAdd(&g_colsum[bj + tid], s);
    }
}

// Final: diag dot + logs + mean. One warp per row.
__global__ void final_kernel(float* __restrict__ out) {
    const float LN2 = 0.6931471805599453f;
    int row = blockIdx.x * 8 + threadIdx.y;
    int lane = threadIdx.x;
    const float4* q = reinterpret_cast<const float4*>(g_qn + (size_t)row * ND);
    const float4* d = reinterpret_cast<const float4*>(g_dn + (size_t)row * ND);
    float4 a0 = q[lane], a1 = q[lane + 32];
    float4 b0 = d[lane], b1 = d[lane + 32];
    float dot = a0.x * b0.x + a0.y * b0.y + a0.z * b0.z + a0.w * b0.w
              + a1.x * b1.x + a1.y * b1.y + a1.z * b1.z + a1.w * b1.w;
#pragma unroll
    for (int o = 16; o > 0; o >>= 1) dot += __shfl_xor_sync(0xFFFFFFFFu, dot, o);
    if (lane == 0) {
        // g_qn is scaled by log2e/T, so s_ii = dot * ln2
        float diag = dot * LN2;
        float term = 0.5f * (logf(g_rowsum[row]) + logf(g_colsum[row])) - diag;
        atomicAdd(out, term * (1.0f / NB));
    }
}

extern "C" void kernel_launch(void* const* d_in, const int* in_sizes, int n_in,
                              void* d_out, int out_size) {
    const float* q = (const float*)d_in[0];
    const float* db = (const float*)d_in[1];
    float* out = (float*)d_out;

    const float K = 1.4426950408889634f / 0.07f;  // log2(e)/T folded into Q

    float* qn; float* dn;
    cudaGetSymbolAddress((void**)&qn, g_qn);
    cudaGetSymbolAddress((void**)&dn, g_dn);

    zero_kernel<<<(NB + 255) / 256, 256>>>(out);

    dim3 nblk(NB / 8);
    dim3 nthr(32, 8);
    normalize_kernel<<<nblk, nthr>>>(q, qn, K);
    normalize_kernel<<<nblk, nthr>>>(db, dn, 1.0f);

    dim3 ggrid(NB / BN, NB / BM);
    gemm_lse_kernel<<<ggrid, 256>>>();

    final_kernel<<<nblk, nthr>>>(out);
}

// round 3
// speedup vs baseline: 11.4398x; 11.4398x over previous
#include <cuda_runtime.h>
#include <cuda_bf16.h>
#include <cstdint>
#include <math.h>

#define NB 16384
#define ND 256

static __device__ __nv_bfloat16 g_qh[NB * ND];  // normalized Q * log2(e)/T, bf16
static __device__ __nv_bfloat16 g_dh[NB * ND];  // normalized D, bf16
static __device__ float g_rowsum[NB];
static __device__ float g_colsum[NB];

__device__ __forceinline__ uint32_t smem_u32(const void* p) {
    uint32_t a;
    asm("{ .reg .u64 t; cvta.to.shared.u64 t, %1; cvt.u32.u64 %0, t; }" : "=r"(a) : "l"(p));
    return a;
}
__device__ __forceinline__ float ex2_approx(float x) {
    float r; asm("ex2.approx.f32 %0, %1;" : "=f"(r) : "f"(x)); return r;
}

// ---------------- setup kernels ----------------
__global__ void zero_kernel(float* out) {
    int i = blockIdx.x * blockDim.x + threadIdx.x;
    if (i < NB) { g_rowsum[i] = 0.0f; g_colsum[i] = 0.0f; }
    if (i == 0) out[0] = 0.0f;
}

// one warp per row: L2-normalize, scale, convert to bf16
__global__ void normalize_kernel(const float* __restrict__ in,
                                 __nv_bfloat16* __restrict__ out, float scale) {
    int row = blockIdx.x * 8 + threadIdx.y;
    int lane = threadIdx.x;
    const float4* src = reinterpret_cast<const float4*>(in + (size_t)row * ND);
    float4 v0 = src[lane];
    float4 v1 = src[lane + 32];
    float ss = v0.x * v0.x + v0.y * v0.y + v0.z * v0.z + v0.w * v0.w
             + v1.x * v1.x + v1.y * v1.y + v1.z * v1.z + v1.w * v1.w;
#pragma unroll
    for (int o = 16; o > 0; o >>= 1) ss += __shfl_xor_sync(0xFFFFFFFFu, ss, o);
    float inv = scale / fmaxf(sqrtf(ss), 1e-12f);
    __nv_bfloat162* dst = reinterpret_cast<__nv_bfloat162*>(out + (size_t)row * ND);
    dst[lane * 2 + 0]  = __floats2bfloat162_rn(v0.x * inv, v0.y * inv);
    dst[lane * 2 + 1]  = __floats2bfloat162_rn(v0.z * inv, v0.w * inv);
    dst[lane * 2 + 64] = __floats2bfloat162_rn(v1.x * inv, v1.y * inv);
    dst[lane * 2 + 65] = __floats2bfloat162_rn(v1.z * inv, v1.w * inv);
}

// ---------------- fused mma.sync GEMM + exp2 + row/col sums ----------------
// CTA tile 128x128, K chunks of 64, double-buffered cp.async.
// SMEM per stage: A 128x64 bf16 (16KB, 128B rows, SW128) + B same = 32KB; 2 stages = 64KB.
#define SMEM_DYN 65536

__global__ void __launch_bounds__(256, 2) gemm_lse_kernel() {
    extern __shared__ char smem[];
    uint32_t sbase = smem_u32(smem);
    int tid = threadIdx.x;
    int wid = tid >> 5, lid = tid & 31;
    int wr = wid & 3, wc = wid >> 2;   // warp tile: rows wr*32..+32, cols wc*64..+64
    int bi = blockIdx.y * 128, bj = blockIdx.x * 128;

    const char* Abase = (const char*)(g_qh + (size_t)bi * ND);
    const char* Bbase = (const char*)(g_dh + (size_t)bj * ND);

    float acc[2][8][4];
#pragma unroll
    for (int mt = 0; mt < 2; mt++)
#pragma unroll
        for (int nt = 0; nt < 8; nt++)
#pragma unroll
            for (int j = 0; j < 4; j++) acc[mt][nt][j] = 0.0f;

    // ---- async tile loader: chunk c (k-range c*64..c*64+64) into stage s ----
    auto load_chunk = [&](int c, int s) {
#pragma unroll
        for (int i = 0; i < 4; i++) {
            int idx = tid + i * 256;               // 0..1023
            int row = idx >> 3;                    // 0..127
            int kb = (idx & 7) * 16;               // byte offset in 128B row
            uint32_t soff = (uint32_t)(row * 128 + kb);
            soff ^= (soff >> 3) & 0x70;            // SW128
            uint64_t ga = (uint64_t)__cvta_generic_to_global(Abase + row * 512 + c * 128 + kb);
            uint64_t gb = (uint64_t)__cvta_generic_to_global(Bbase + row * 512 + c * 128 + kb);
            asm volatile("cp.async.cg.shared.global [%0], [%1], 16;"
                         :: "r"(sbase + s * 32768 + soff), "l"(ga));
            asm volatile("cp.async.cg.shared.global [%0], [%1], 16;"
                         :: "r"(sbase + s * 32768 + 16384 + soff), "l"(gb));
        }
        asm volatile("cp.async.commit_group;");
    };

    load_chunk(0, 0);

    for (int c = 0; c < 4; c++) {
        if (c < 3) {
            load_chunk(c + 1, (c + 1) & 1);
            asm volatile("cp.async.wait_group 1;");
        } else {
            asm volatile("cp.async.wait_group 0;");
        }
        __syncthreads();

        uint32_t aS = sbase + (c & 1) * 32768;
        uint32_t bS = aS + 16384;

#pragma unroll
        for (int ks = 0; ks < 4; ks++) {
            int kb = ks * 32 + ((lid >> 4) & 1) * 16;
            uint32_t a[2][4], b[8][2];
#pragma unroll
            for (int mt = 0; mt < 2; mt++) {
                int r = wr * 32 + mt * 16 + (lid & 7) + ((lid >> 3) & 1) * 8;
                uint32_t off = (uint32_t)(r * 128 + kb);
                off ^= (off >> 3) & 0x70;
                asm volatile("ldmatrix.sync.aligned.m8n8.x4.shared.b16 {%0,%1,%2,%3}, [%4];"
                             : "=r"(a[mt][0]), "=r"(a[mt][1]), "=r"(a[mt][2]), "=r"(a[mt][3])
                             : "r"(aS + off));
            }
#pragma unroll
            for (int np = 0; np < 4; np++) {
                int r = wc * 64 + np * 16 + (lid & 7) + ((lid >> 3) & 1) * 8;
                uint32_t off = (uint32_t)(r * 128 + kb);
                off ^= (off >> 3) & 0x70;
                uint32_t r0, r1, r2, r3;
                asm volatile("ldmatrix.sync.aligned.m8n8.x4.shared.b16 {%0,%1,%2,%3}, [%4];"
                             : "=r"(r0), "=r"(r1), "=r"(r2), "=r"(r3)
                             : "r"(bS + off));
                b[2 * np][0] = r0; b[2 * np + 1][0] = r1;
                b[2 * np][1] = r2; b[2 * np + 1][1] = r3;
            }
#pragma unroll
            for (int mt = 0; mt < 2; mt++)
#pragma unroll
                for (int nt = 0; nt < 8; nt++)
                    asm volatile(
                        "mma.sync.aligned.m16n8k16.row.col.f32.bf16.bf16.f32 "
                        "{%0,%1,%2,%3}, {%4,%5,%6,%7}, {%8,%9}, {%0,%1,%2,%3};"
                        : "+f"(acc[mt][nt][0]), "+f"(acc[mt][nt][1]),
                          "+f"(acc[mt][nt][2]), "+f"(acc[mt][nt][3])
                        : "r"(a[mt][0]), "r"(a[mt][1]), "r"(a[mt][2]), "r"(a[mt][3]),
                          "r"(b[nt][0]), "r"(b[nt][1]));
        }
        __syncthreads();
    }

    // ---- epilogue: exp2, per-lane row/col partials, warp shuffles, atomics ----
    // C fragment m16n8k16: lane l holds rows (l>>2), (l>>2)+8 of the 16-row tile,
    // cols (l&3)*2, +1 of the 8-col tile.
    float rsum[2][2];  // [mt][row half]
    float csum[8][2];  // [nt][col parity]
#pragma unroll
    for (int mt = 0; mt < 2; mt++) { rsum[mt][0] = 0.0f; rsum[mt][1] = 0.0f; }
#pragma unroll
    for (int nt = 0; nt < 8; nt++) { csum[nt][0] = 0.0f; csum[nt][1] = 0.0f; }

#pragma unroll
    for (int mt = 0; mt < 2; mt++)
#pragma unroll
        for (int nt = 0; nt < 8; nt++) {
            float e0 = ex2_approx(acc[mt][nt][0]);
            float e1 = ex2_approx(acc[mt][nt][1]);
            float e2 = ex2_approx(acc[mt][nt][2]);
            float e3 = ex2_approx(acc[mt][nt][3]);
            rsum[mt][0] += e0 + e1;
            rsum[mt][1] += e2 + e3;
            csum[nt][0] += e0 + e2;
            csum[nt][1] += e1 + e3;
        }

    // rows: reduce across the lane quad (lanes sharing l>>2)
#pragma unroll
    for (int mt = 0; mt < 2; mt++)
#pragma unroll
        for (int h = 0; h < 2; h++) {
            float v = rsum[mt][h];
            v += __shfl_xor_sync(0xFFFFFFFFu, v, 1);
            v += __shfl_xor_sync(0xFFFFFFFFu, v, 2);
            rsum[mt][h] = v;
        }
    if ((lid & 3) == 0) {
        int r = bi + wr * 32 + (lid >> 2);
        atomicAdd(&g_rowsum[r + 0],  rsum[0][0]);
        atomicAdd(&g_rowsum[r + 8],  rsum[0][1]);
        atomicAdd(&g_rowsum[r + 16], rsum[1][0]);
        atomicAdd(&g_rowsum[r + 24], rsum[1][1]);
    }

    // cols: reduce across lanes sharing l&3 (xor 4, 8, 16)
#pragma unroll
    for (int nt = 0; nt < 8; nt++)
#pragma unroll
        for (int j = 0; j < 2; j++) {
            float v = csum[nt][j];
            v += __shfl_xor_sync(0xFFFFFFFFu, v, 4);
            v += __shfl_xor_sync(0xFFFFFFFFu, v, 8);
            v += __shfl_xor_sync(0xFFFFFFFFu, v, 16);
            csum[nt][j] = v;
        }
    if (lid < 4) {
        int cb = bj + wc * 64 + lid * 2;
#pragma unroll
        for (int nt = 0; nt < 8; nt++) {
            atomicAdd(&g_colsum[cb + nt * 8 + 0], csum[nt][0]);
            atomicAdd(&g_colsum[cb + nt * 8 + 1], csum[nt][1]);
        }
    }
}

// ---------------- final: exact fp32 diagonal + logs + mean ----------------
__global__ void final_kernel(const float* __restrict__ q, const float* __restrict__ d,
                             float* __restrict__ out) {
    int row = blockIdx.x * 8 + threadIdx.y;
    int lane = threadIdx.x;
    const float4* qs = reinterpret_cast<const float4*>(q + (size_t)row * ND);
    const float4* ds = reinterpret_cast<const float4*>(d + (size_t)row * ND);
    float4 a0 = qs[lane], a1 = qs[lane + 32];
    float4 b0 = ds[lane], b1 = ds[lane + 32];
    float sq = a0.x * a0.x + a0.y * a0.y + a0.z * a0.z + a0.w * a0.w
             + a1.x * a1.x + a1.y * a1.y + a1.z * a1.z + a1.w * a1.w;
    float sd = b0.x * b0.x + b0.y * b0.y + b0.z * b0.z + b0.w * b0.w
             + b1.x * b1.x + b1.y * b1.y + b1.z * b1.z + b1.w * b1.w;
    float dot = a0.x * b0.x + a0.y * b0.y + a0.z * b0.z + a0.w * b0.w
              + a1.x * b1.x + a1.y * b1.y + a1.z * b1.z + a1.w * b1.w;
#pragma unroll
    for (int o = 16; o > 0; o >>= 1) {
        sq += __shfl_xor_sync(0xFFFFFFFFu, sq, o);
        sd += __shfl_xor_sync(0xFFFFFFFFu, sd, o);
        dot += __shfl_xor_sync(0xFFFFFFFFu, dot, o);
    }
    if (lane == 0) {
        float nq = fmaxf(sqrtf(sq), 1e-12f);
        float nd = fmaxf(sqrtf(sd), 1e-12f);
        float diag = dot / (nq * nd) * (1.0f / 0.07f);
        float term = 0.5f * (logf(g_rowsum[row]) + logf(g_colsum[row])) - diag;
        atomicAdd(out, term * (1.0f / NB));
    }
}

extern "C" void kernel_launch(void* const* d_in, const int* in_sizes, int n_in,
                              void* d_out, int out_size) {
    const float* q = (const float*)d_in[0];
    const float* db = (const float*)d_in[1];
    float* out = (float*)d_out;

    const float K = 1.4426950408889634f / 0.07f;  // log2(e)/T folded into Q

    __nv_bfloat16* qh; __nv_bfloat16* dh;
    cudaGetSymbolAddress((void**)&qh, g_qh);
    cudaGetSymbolAddress((void**)&dh, g_dh);

    static bool attr_set = false;
    if (!attr_set) {
        cudaFuncSetAttribute(gemm_lse_kernel, cudaFuncAttributeMaxDynamicSharedMemorySize, SMEM_DYN);
        attr_set = true;
    }

    zero_kernel<<<(NB + 255) / 256, 256>>>(out);

    dim3 nblk(NB / 8);
    dim3 nthr(32, 8);
    normalize_kernel<<<nblk, nthr>>>(q, qh, K);
    normalize_kernel<<<nblk, nthr>>>(db, dh, 1.0f);

    dim3 ggrid(NB / 128, NB / 128);
    gemm_lse_kernel<<<ggrid, 256, SMEM_DYN>>>();

    final_kernel<<<nblk, nthr>>>(q, db, out);
}

// round 4
// speedup vs baseline: 12.2224x; 1.0684x over previous
#include <cuda_runtime.h>
#include <cuda_bf16.h>
#include <cstdint>
#include <math.h>

#define NB 16384
#define ND 256

static __device__ __nv_bfloat16 g_qh[NB * ND];  // normalized Q * log2(e)/T, bf16
static __device__ __nv_bfloat16 g_dh[NB * ND];  // normalized D, bf16
static __device__ float g_rowsum[NB];
static __device__ float g_colsum[NB];

__device__ __forceinline__ uint32_t smem_u32(const void* p) {
    uint32_t a;
    asm("{ .reg .u64 t; cvta.to.shared.u64 t, %1; cvt.u32.u64 %0, t; }" : "=r"(a) : "l"(p));
    return a;
}
__device__ __forceinline__ float ex2_approx(float x) {
    float r; asm("ex2.approx.f32 %0, %1;" : "=f"(r) : "f"(x)); return r;
}

// ---------------- setup kernels ----------------
__global__ void zero_kernel(float* out) {
    int i = blockIdx.x * blockDim.x + threadIdx.x;
    if (i < NB) { g_rowsum[i] = 0.0f; g_colsum[i] = 0.0f; }
    if (i == 0) out[0] = 0.0f;
}

// one warp per row: L2-normalize, scale, convert to bf16
__global__ void normalize_kernel(const float* __restrict__ in,
                                 __nv_bfloat16* __restrict__ out, float scale) {
    int row = blockIdx.x * 8 + threadIdx.y;
    int lane = threadIdx.x;
    const float4* src = reinterpret_cast<const float4*>(in + (size_t)row * ND);
    float4 v0 = src[lane];
    float4 v1 = src[lane + 32];
    float ss = v0.x * v0.x + v0.y * v0.y + v0.z * v0.z + v0.w * v0.w
             + v1.x * v1.x + v1.y * v1.y + v1.z * v1.z + v1.w * v1.w;
#pragma unroll
    for (int o = 16; o > 0; o >>= 1) ss += __shfl_xor_sync(0xFFFFFFFFu, ss, o);
    float inv = scale / fmaxf(sqrtf(ss), 1e-12f);
    __nv_bfloat162* dst = reinterpret_cast<__nv_bfloat162*>(out + (size_t)row * ND);
    dst[lane * 2 + 0]  = __floats2bfloat162_rn(v0.x * inv, v0.y * inv);
    dst[lane * 2 + 1]  = __floats2bfloat162_rn(v0.z * inv, v0.w * inv);
    dst[lane * 2 + 64] = __floats2bfloat162_rn(v1.x * inv, v1.y * inv);
    dst[lane * 2 + 65] = __floats2bfloat162_rn(v1.z * inv, v1.w * inv);
}

// ---------------- fused mma.sync GEMM + exp2 + row/col sums ----------------
// CTA tile 128x128, K chunks of 64, 3-stage cp.async pipeline.
// SMEM per stage: A 16KB + B 16KB = 32KB; 3 stages = 96KB.
#define STAGE_BYTES 32768
#define SMEM_DYN (3 * STAGE_BYTES)

__global__ void __launch_bounds__(256, 2) gemm_lse_kernel() {
    extern __shared__ char smem[];
    uint32_t sbase = smem_u32(smem);
    int tid = threadIdx.x;
    int wid = tid >> 5, lid = tid & 31;
    int wr = wid & 3, wc = wid >> 2;   // warp tile: rows wr*32..+32, cols wc*64..+64
    int bi = blockIdx.y * 128, bj = blockIdx.x * 128;

    // ---- loader precompute (strength-reduced SW128) ----
    // thread handles rows r0 + i*32 (i=0..3), fixed 16B column kb within 128B row.
    int r0 = tid >> 3;
    int kbl = (tid & 7) * 16;
    uint32_t soff0 = (uint32_t)(r0 * 128 + (kbl ^ ((r0 & 7) << 4)));
    const char* Ag = (const char*)(g_qh + (size_t)bi * ND) + r0 * 512 + kbl;
    const char* Bg = (const char*)(g_dh + (size_t)bj * ND) + r0 * 512 + kbl;

    auto load_chunk = [&](int c, int s) {
        uint32_t sA = sbase + s * STAGE_BYTES + soff0;
        const char* a = Ag + c * 128;
        const char* b = Bg + c * 128;
#pragma unroll
        for (int i = 0; i < 4; i++) {
            asm volatile("cp.async.cg.shared.global [%0], [%1], 16;"
                         :: "r"(sA + i * 4096), "l"(a + i * 16384));
            asm volatile("cp.async.cg.shared.global [%0], [%1], 16;"
                         :: "r"(sA + 16384 + i * 4096), "l"(b + i * 16384));
        }
        asm volatile("cp.async.commit_group;");
    };

    float acc[2][8][4];
#pragma unroll
    for (int mt = 0; mt < 2; mt++)
#pragma unroll
        for (int nt = 0; nt < 8; nt++)
#pragma unroll
            for (int j = 0; j < 4; j++) acc[mt][nt][j] = 0.0f;

    // ---- ldmatrix precompute ----
    // fragment row within tile: fr = (lid&7) + ((lid>>3)&1)*8 ; per-thread swizzle const
    int fr = (lid & 7) + ((lid >> 3) & 1) * 8;
    uint32_t cswz = (uint32_t)((lid & 7) << 4);
    uint32_t hi16 = ((lid >> 4) & 1) * 16;
    // row-base byte offsets (relative to stage A/B base)
    uint32_t rbA[2], rbB[4];
#pragma unroll
    for (int mt = 0; mt < 2; mt++) rbA[mt] = (uint32_t)((wr * 32 + mt * 16 + fr) * 128);
#pragma unroll
    for (int np = 0; np < 4; np++) rbB[np] = (uint32_t)((wc * 64 + np * 16 + fr) * 128);

    // ---- prologue: fill 3 stages ----
    load_chunk(0, 0);
    load_chunk(1, 1);
    load_chunk(2, 2);

    for (int c = 0; c < 4; c++) {
        if (c == 0) { asm volatile("cp.async.wait_group 2;"); }
        else if (c == 1) { asm volatile("cp.async.wait_group 2;"); }
        else if (c == 2) { asm volatile("cp.async.wait_group 1;"); }
        else { asm volatile("cp.async.wait_group 0;"); }
        __syncthreads();
        if (c == 1) load_chunk(3, 0);   // after sync: stage 0 fully consumed

        uint32_t aS = sbase + (c % 3) * STAGE_BYTES;
        uint32_t bS = aS + 16384;

#pragma unroll
        for (int ks = 0; ks < 4; ks++) {
            uint32_t kx = ((uint32_t)(ks * 32) + hi16) ^ cswz;
            uint32_t a[2][4], b[8][2];
#pragma unroll
            for (int mt = 0; mt < 2; mt++)
                asm volatile("ldmatrix.sync.aligned.m8n8.x4.shared.b16 {%0,%1,%2,%3}, [%4];"
                             : "=r"(a[mt][0]), "=r"(a[mt][1]), "=r"(a[mt][2]), "=r"(a[mt][3])
                             : "r"(aS + rbA[mt] + kx));
#pragma unroll
            for (int np = 0; np < 4; np++) {
                uint32_t r0_, r1_, r2_, r3_;
                asm volatile("ldmatrix.sync.aligned.m8n8.x4.shared.b16 {%0,%1,%2,%3}, [%4];"
                             : "=r"(r0_), "=r"(r1_), "=r"(r2_), "=r"(r3_)
                             : "r"(bS + rbB[np] + kx));
                b[2 * np][0] = r0_; b[2 * np + 1][0] = r1_;
                b[2 * np][1] = r2_; b[2 * np + 1][1] = r3_;
            }
#pragma unroll
            for (int mt = 0; mt < 2; mt++)
#pragma unroll
                for (int nt = 0; nt < 8; nt++)
                    asm volatile(
                        "mma.sync.aligned.m16n8k16.row.col.f32.bf16.bf16.f32 "
                        "{%0,%1,%2,%3}, {%4,%5,%6,%7}, {%8,%9}, {%0,%1,%2,%3};"
                        : "+f"(acc[mt][nt][0]), "+f"(acc[mt][nt][1]),
                          "+f"(acc[mt][nt][2]), "+f"(acc[mt][nt][3])
                        : "r"(a[mt][0]), "r"(a[mt][1]), "r"(a[mt][2]), "r"(a[mt][3]),
                          "r"(b[nt][0]), "r"(b[nt][1]));
        }
    }

    // ---- epilogue: exp2, per-lane row/col partials, warp shuffles, atomics ----
    float rsum[2][2];  // [mt][row half]
    float csum[8][2];  // [nt][col parity]
#pragma unroll
    for (int mt = 0; mt < 2; mt++) { rsum[mt][0] = 0.0f; rsum[mt][1] = 0.0f; }
#pragma unroll
    for (int nt = 0; nt < 8; nt++) { csum[nt][0] = 0.0f; csum[nt][1] = 0.0f; }

#pragma unroll
    for (int mt = 0; mt < 2; mt++)
#pragma unroll
        for (int nt = 0; nt < 8; nt++) {
            float e0 = ex2_approx(acc[mt][nt][0]);
            float e1 = ex2_approx(acc[mt][nt][1]);
            float e2 = ex2_approx(acc[mt][nt][2]);
            float e3 = ex2_approx(acc[mt][nt][3]);
            rsum[mt][0] += e0 + e1;
            rsum[mt][1] += e2 + e3;
            csum[nt][0] += e0 + e2;
            csum[nt][1] += e1 + e3;
        }

#pragma unroll
    for (int mt = 0; mt < 2; mt++)
#pragma unroll
        for (int h = 0; h < 2; h++) {
            float v = rsum[mt][h];
            v += __shfl_xor_sync(0xFFFFFFFFu, v, 1);
            v += __shfl_xor_sync(0xFFFFFFFFu, v, 2);
            rsum[mt][h] = v;
        }
    if ((lid & 3) == 0) {
        int r = bi + wr * 32 + (lid >> 2);
        atomicAdd(&g_rowsum[r + 0],  rsum[0][0]);
        atomicAdd(&g_rowsum[r + 8],  rsum[0][1]);
        atomicAdd(&g_rowsum[r + 16], rsum[1][0]);
        atomicAdd(&g_rowsum[r + 24], rsum[1][1]);
    }

#pragma unroll
    for (int nt = 0; nt < 8; nt++)
#pragma unroll
        for (int j = 0; j < 2; j++) {
            float v = csum[nt][j];
            v += __shfl_xor_sync(0xFFFFFFFFu, v, 4);
            v += __shfl_xor_sync(0xFFFFFFFFu, v, 8);
            v += __shfl_xor_sync(0xFFFFFFFFu, v, 16);
            csum[nt][j] = v;
        }
    if (lid < 4) {
        int cb = bj + wc * 64 + lid * 2;
#pragma unroll
        for (int nt = 0; nt < 8; nt++) {
            atomicAdd(&g_colsum[cb + nt * 8 + 0], csum[nt][0]);
            atomicAdd(&g_colsum[cb + nt * 8 + 1], csum[nt][1]);
        }
    }
}

// ---------------- final: exact fp32 diagonal + logs + mean ----------------
__global__ void final_kernel(const float* __restrict__ q, const float* __restrict__ d,
                             float* __restrict__ out) {
    int row = blockIdx.x * 8 + threadIdx.y;
    int lane = threadIdx.x;
    const float4* qs = reinterpret_cast<const float4*>(q + (size_t)row * ND);
    const float4* ds = reinterpret_cast<const float4*>(d + (size_t)row * ND);
    float4 a0 = qs[lane], a1 = qs[lane + 32];
    float4 b0 = ds[lane], b1 = ds[lane + 32];
    float sq = a0.x * a0.x + a0.y * a0.y + a0.z * a0.z + a0.w * a0.w
             + a1.x * a1.x + a1.y * a1.y + a1.z * a1.z + a1.w * a1.w;
    float sd = b0.x * b0.x + b0.y * b0.y + b0.z * b0.z + b0.w * b0.w
             + b1.x * b1.x + b1.y * b1.y + b1.z * b1.z + b1.w * b1.w;
    float dot = a0.x * b0.x + a0.y * b0.y + a0.z * b0.z + a0.w * b0.w
              + a1.x * b1.x + a1.y * b1.y + a1.z * b1.z + a1.w * b1.w;
#pragma unroll
    for (int o = 16; o > 0; o >>= 1) {
        sq += __shfl_xor_sync(0xFFFFFFFFu, sq, o);
        sd += __shfl_xor_sync(0xFFFFFFFFu, sd, o);
        dot += __shfl_xor_sync(0xFFFFFFFFu, dot, o);
    }
    if (lane == 0) {
        float nq = fmaxf(sqrtf(sq), 1e-12f);
        float nd = fmaxf(sqrtf(sd), 1e-12f);
        float diag = dot / (nq * nd) * (1.0f / 0.07f);
        float term = 0.5f * (logf(g_rowsum[row]) + logf(g_colsum[row])) - diag;
        atomicAdd(out, term * (1.0f / NB));
    }
}

extern "C" void kernel_launch(void* const* d_in, const int* in_sizes, int n_in,
                              void* d_out, int out_size) {
    const float* q = (const float*)d_in[0];
    const float* db = (const float*)d_in[1];
    float* out = (float*)d_out;

    const float K = 1.4426950408889634f / 0.07f;  // log2(e)/T folded into Q

    __nv_bfloat16* qh; __nv_bfloat16* dh;
    cudaGetSymbolAddress((void**)&qh, g_qh);
    cudaGetSymbolAddress((void**)&dh, g_dh);

    static bool attr_set = false;
    if (!attr_set) {
        cudaFuncSetAttribute(gemm_lse_kernel, cudaFuncAttributeMaxDynamicSharedMemorySize, SMEM_DYN);
        attr_set = true;
    }

    zero_kernel<<<(NB + 255) / 256, 256>>>(out);

    dim3 nblk(NB / 8);
    dim3 nthr(32, 8);
    normalize_kernel<<<nblk, nthr>>>(q, qh, K);
    normalize_kernel<<<nblk, nthr>>>(db, dh, 1.0f);

    dim3 ggrid(NB / 128, NB / 128);
    gemm_lse_kernel<<<ggrid, 256, SMEM_DYN>>>();

    final_kernel<<<nblk, nthr>>>(q, db, out);
}